// round 4
// baseline (speedup 1.0000x reference)
#include <cuda_runtime.h>
#include <math.h>

using u64 = unsigned long long;

// ---------------------------------------------------------------------------
// Packed fp32x2 helpers (sm_103a FFMA2 — only reachable via PTX).
// ---------------------------------------------------------------------------
__device__ __forceinline__ u64 pack_dup(float v) {
    u64 r; asm("mov.b64 %0, {%1, %1};" : "=l"(r) : "f"(v)); return r;
}
__device__ __forceinline__ void unpack2(u64 p, float& lo, float& hi) {
    asm("mov.b64 {%0, %1}, %2;" : "=f"(lo), "=f"(hi) : "l"(p));
}
__device__ __forceinline__ u64 ffma2(u64 a, u64 b, u64 c) {
    u64 d; asm("fma.rn.f32x2 %0, %1, %2, %3;" : "=l"(d) : "l"(a), "l"(b), "l"(c));
    return d;
}

// ---------------------------------------------------------------------------
// Scratch (no allocation allowed): masked weights + scan barrier counters.
// ---------------------------------------------------------------------------
__device__ float g_Wc[1024 * 1024];   // kernel * u_current            [D, U]
__device__ float g_Wp[1024 * 1024];   // recurrent_kernel * u_previous [U, U]
__device__ unsigned g_bar[8];         // per-m-group barrier counters

__global__ void zero_bar_kernel() {
    if (threadIdx.x < 8) g_bar[threadIdx.x] = 0u;
}

// ---------------------------------------------------------------------------
// Build masked weights. One block per unit (column u).
// ---------------------------------------------------------------------------
__global__ void build_mask_kernel(const float* __restrict__ W,
                                  const float* __restrict__ mu,
                                  const float* __restrict__ sigma,
                                  float* __restrict__ Wm,
                                  int n_in, int units, float scale) {
    int u = blockIdx.x;
    float m = mu[u];
    float s = sigma[u];
    s = fminf(fmaxf(s, 0.01f), 1.0f);
    float inv2s2 = 1.0f / (2.0f * s * s);
    float inv_nm1 = 1.0f / (float)(n_in - 1);

    float ss = 0.0f;
    for (int d = threadIdx.x; d < n_in; d += blockDim.x) {
        float diff = (float)d * inv_nm1 - m;
        float e = expf(-diff * diff * inv2s2);
        ss += e * e;
    }
    __shared__ float red[32];
    #pragma unroll
    for (int o = 16; o > 0; o >>= 1) ss += __shfl_down_sync(0xffffffffu, ss, o);
    if ((threadIdx.x & 31) == 0) red[threadIdx.x >> 5] = ss;
    __syncthreads();
    if (threadIdx.x < 32) {
        int nwarp = (blockDim.x + 31) >> 5;
        float v = (threadIdx.x < nwarp) ? red[threadIdx.x] : 0.0f;
        #pragma unroll
        for (int o = 16; o > 0; o >>= 1) v += __shfl_down_sync(0xffffffffu, v, o);
        if (threadIdx.x == 0) red[0] = v;
    }
    __syncthreads();
    float factor = scale * rsqrtf(red[0]);

    for (int d = threadIdx.x; d < n_in; d += blockDim.x) {
        float diff = (float)d * inv_nm1 - m;
        float e = expf(-diff * diff * inv2s2);
        Wm[(size_t)d * units + u] = W[(size_t)d * units + u] * (e * factor);
    }
}

// ---------------------------------------------------------------------------
// Big GEMM: C = A @ B + bias.  128x128x16 tiles, 256 threads, 8x8 micro-tile
// via FFMA2 (M-pairs).
// ---------------------------------------------------------------------------
__global__ void __launch_bounds__(256) gemm_big_kernel(
    const float* __restrict__ A, int lda,
    const float* __restrict__ Bm,
    const float* __restrict__ bias,
    float* __restrict__ C, int ldc,
    int N, int K)
{
    __shared__ __align__(16) float As[16][128];   // transposed A tile [k][m]
    __shared__ __align__(16) float Bs[16][128];   // B tile [k][n]

    const int tid = threadIdx.x;
    const int tx = tid & 15;
    const int ty = tid >> 4;
    const int m0 = blockIdx.y * 128;
    const int n0 = blockIdx.x * 128;
    const int mt = ty * 8;
    const int nt = tx * 8;

    const int aRow = tid >> 2;
    const int aCol = (tid & 3) * 4;
    const int bRow = tid >> 5;
    const int bCol = (tid & 31) * 4;

    u64 acc[4][8];
    #pragma unroll
    for (int i = 0; i < 4; i++)
        #pragma unroll
        for (int j = 0; j < 8; j++) acc[i][j] = 0ull;

    for (int k0 = 0; k0 < K; k0 += 16) {
        #pragma unroll
        for (int r = 0; r < 2; r++) {
            int mr = aRow + r * 64;
            float4 v = *(const float4*)&A[(size_t)(m0 + mr) * lda + k0 + aCol];
            As[aCol + 0][mr] = v.x;
            As[aCol + 1][mr] = v.y;
            As[aCol + 2][mr] = v.z;
            As[aCol + 3][mr] = v.w;
        }
        #pragma unroll
        for (int r = 0; r < 2; r++) {
            int kr = bRow + r * 8;
            *(float4*)&Bs[kr][bCol] =
                *(const float4*)&Bm[(size_t)(k0 + kr) * N + n0 + bCol];
        }
        __syncthreads();

        #pragma unroll
        for (int kk = 0; kk < 16; kk++) {
            ulonglong2 a01 = *(const ulonglong2*)&As[kk][mt];
            ulonglong2 a23 = *(const ulonglong2*)&As[kk][mt + 4];
            float4 b0 = *(const float4*)&Bs[kk][nt];
            float4 b1 = *(const float4*)&Bs[kk][nt + 4];
            u64 ap[4] = {a01.x, a01.y, a23.x, a23.y};
            u64 bd[8] = {pack_dup(b0.x), pack_dup(b0.y), pack_dup(b0.z), pack_dup(b0.w),
                         pack_dup(b1.x), pack_dup(b1.y), pack_dup(b1.z), pack_dup(b1.w)};
            #pragma unroll
            for (int i = 0; i < 4; i++)
                #pragma unroll
                for (int j = 0; j < 8; j++)
                    acc[i][j] = ffma2(ap[i], bd[j], acc[i][j]);
        }
        __syncthreads();
    }

    float bv[8];
    {
        float4 b0 = *(const float4*)&bias[n0 + nt];
        float4 b1 = *(const float4*)&bias[n0 + nt + 4];
        bv[0] = b0.x; bv[1] = b0.y; bv[2] = b0.z; bv[3] = b0.w;
        bv[4] = b1.x; bv[5] = b1.y; bv[6] = b1.z; bv[7] = b1.w;
    }
    #pragma unroll
    for (int i = 0; i < 4; i++) {
        float lo[8], hi[8];
        #pragma unroll
        for (int j = 0; j < 8; j++) unpack2(acc[i][j], lo[j], hi[j]);
        const int mr = m0 + mt + 2 * i;
        float* c0 = &C[(size_t)mr * ldc + n0 + nt];
        float* c1 = &C[(size_t)(mr + 1) * ldc + n0 + nt];
        *(float4*)&c0[0] = make_float4(lo[0] + bv[0], lo[1] + bv[1], lo[2] + bv[2], lo[3] + bv[3]);
        *(float4*)&c0[4] = make_float4(lo[4] + bv[4], lo[5] + bv[5], lo[6] + bv[6], lo[7] + bv[7]);
        *(float4*)&c1[0] = make_float4(hi[0] + bv[0], hi[1] + bv[1], hi[2] + bv[2], hi[3] + bv[3]);
        *(float4*)&c1[4] = make_float4(hi[4] + bv[4], hi[5] + bv[5], hi[6] + bv[6], hi[7] + bv[7]);
    }
}

// ---------------------------------------------------------------------------
// Persistent scan kernel.
// Grid: 32 n-blocks (x) * 4 m-blocks (y) = 128 CTAs, 256 threads each.
// Each CTA: owns columns [32*nb, 32*nb+32) of Wp (resident in SMEM all T
// steps) and rows [64*mb, 64*mb+64) of the batch.
// Per step: h_t(tile) = tanh(Z_t(tile) + h_{t-1}[rows,:] @ Wp_slice),
// written in place over Z in d_out. Per-m-group barrier (32 CTAs) per step.
// SMEM: Wp slice 128KB + dup'd h-tile 32KB = 160KB (1 CTA/SM, all resident).
// ---------------------------------------------------------------------------
__global__ void __launch_bounds__(256, 1) scan_kernel(
    float* __restrict__ out, const float* __restrict__ h0,
    const float* __restrict__ Wp, int T, int U)
{
    extern __shared__ float smem[];
    float* Wp_s = smem;               // [1024][32]
    float* hs   = smem + 1024 * 32;   // [64][128]  (64 rows duplicated)

    const int tid = threadIdx.x;
    const int nb = blockIdx.x;        // 0..31
    const int mb = blockIdx.y;        // 0..3
    const int n0 = nb * 32;
    const int m0 = mb * 64;
    const size_t ldo = (size_t)T * U;

    // Load resident Wp slice: 1024 x 32 floats.
    #pragma unroll 4
    for (int i = 0; i < 32; i++) {
        int k = (tid >> 3) + 32 * i;
        int c = (tid & 7) * 4;
        *(float4*)&Wp_s[k * 32 + c] = *(const float4*)&Wp[(size_t)k * U + n0 + c];
    }

    const int tx = tid & 7;           // cols n0 + 4*tx .. +3  (2 N-pairs)
    const int ry = tid >> 3;          // rows m0 + 2*ry, 2*ry+1
    const int lrow = tid & 63;        // staging: this thread's h row
    const int kq = tid >> 6;          // staging: k quadrant (16 cols)

    for (int t = 0; t < T; t++) {
        const float* hsrc;
        size_t ldh;
        if (t == 0) { hsrc = h0; ldh = U; }
        else        { hsrc = out + (size_t)(t - 1) * U; ldh = ldo; }

        u64 acc00 = 0ull, acc01 = 0ull, acc10 = 0ull, acc11 = 0ull;

        for (int tile = 0; tile < 16; tile++) {
            const int k0 = tile * 64;
            // Prefetch this thread's 16 h values (1 row x 16 k).
            float4 r[4];
            const float* src = hsrc + (size_t)(m0 + lrow) * ldh + k0 + kq * 16;
            #pragma unroll
            for (int j = 0; j < 4; j++) r[j] = *(const float4*)&src[4 * j];

            __syncthreads();   // previous tile fully consumed
            #pragma unroll
            for (int j = 0; j < 4; j++) {
                const int kl = kq * 16 + 4 * j;
                *(u64*)&hs[(kl + 0) * 128 + 2 * lrow] = pack_dup(r[j].x);
                *(u64*)&hs[(kl + 1) * 128 + 2 * lrow] = pack_dup(r[j].y);
                *(u64*)&hs[(kl + 2) * 128 + 2 * lrow] = pack_dup(r[j].z);
                *(u64*)&hs[(kl + 3) * 128 + 2 * lrow] = pack_dup(r[j].w);
            }
            __syncthreads();   // tile staged

            #pragma unroll 8
            for (int kk = 0; kk < 64; kk++) {
                ulonglong2 a = *(const ulonglong2*)&hs[kk * 128 + 4 * ry];
                ulonglong2 b = *(const ulonglong2*)&Wp_s[(k0 + kk) * 32 + 4 * tx];
                acc00 = ffma2(a.x, b.x, acc00);
                acc01 = ffma2(a.x, b.y, acc01);
                acc10 = ffma2(a.y, b.x, acc10);
                acc11 = ffma2(a.y, b.y, acc11);
            }
        }

        // Epilogue: += Z (in d_out), tanh, store in place.
        {
            float* p0 = out + (size_t)(m0 + 2 * ry) * ldo + (size_t)t * U + n0 + 4 * tx;
            float* p1 = p0 + ldo;
            float4 z0 = *(const float4*)p0;
            float4 z1 = *(const float4*)p1;
            float lo, hi;
            float4 o0, o1;
            unpack2(acc00, lo, hi); o0.x = tanhf(z0.x + lo); o0.y = tanhf(z0.y + hi);
            unpack2(acc01, lo, hi); o0.z = tanhf(z0.z + lo); o0.w = tanhf(z0.w + hi);
            unpack2(acc10, lo, hi); o1.x = tanhf(z1.x + lo); o1.y = tanhf(z1.y + hi);
            unpack2(acc11, lo, hi); o1.z = tanhf(z1.z + lo); o1.w = tanhf(z1.w + hi);
            *(float4*)p0 = o0;
            *(float4*)p1 = o1;
        }

        // Per-m-group barrier: 32 CTAs (all nb of this mb).
        __threadfence();
        __syncthreads();
        if (tid == 0) {
            atomicAdd(&g_bar[mb], 1u);
            const unsigned target = 32u * (unsigned)(t + 1);
            unsigned v;
            do {
                asm volatile("ld.acquire.gpu.u32 %0, [%1];"
                             : "=r"(v) : "l"(&g_bar[mb]));
            } while (v < target);
        }
        __syncthreads();
    }
}

// ---------------------------------------------------------------------------
// Launch.
// Inputs: 0 inputs [B,T,D]  1 h0 [B,U]  2 kernel [D,U]  3 rec_kernel [U,U]
//         4 bias [U]  5 mu_c [U]  6 sigma_c [U]  7 mu_p [U]  8 sigma_p [U]
// Output: [B,T,U] float32.
// ---------------------------------------------------------------------------
extern "C" void kernel_launch(void* const* d_in, const int* in_sizes, int n_in,
                              void* d_out, int out_size) {
    const float* X    = (const float*)d_in[0];
    const float* h0   = (const float*)d_in[1];
    const float* Wk   = (const float*)d_in[2];
    const float* Wr   = (const float*)d_in[3];
    const float* bias = (const float*)d_in[4];
    const float* muc  = (const float*)d_in[5];
    const float* sic  = (const float*)d_in[6];
    const float* mup  = (const float*)d_in[7];
    const float* sip  = (const float*)d_in[8];
    float* out = (float*)d_out;

    const int U = in_sizes[4];
    const int D = in_sizes[2] / U;
    const int B = in_sizes[1] / U;
    const int T = in_sizes[0] / (B * D);

    float* Wc;
    float* Wp;
    cudaGetSymbolAddress((void**)&Wc, g_Wc);
    cudaGetSymbolAddress((void**)&Wp, g_Wp);

    static int s_attr_done = 0;
    const int scan_smem = (1024 * 32 + 64 * 128) * (int)sizeof(float);  // 160KB
    if (!s_attr_done) {
        cudaFuncSetAttribute(scan_kernel,
                             cudaFuncAttributeMaxDynamicSharedMemorySize,
                             scan_smem);
        s_attr_done = 1;
    }

    const float scale = sqrtf((float)D);  // reference uses sqrt(D) for BOTH masks

    // 0) Reset barrier counters (deterministic per launch/replay).
    zero_bar_kernel<<<1, 32>>>();

    // 1) Masked weights.
    build_mask_kernel<<<U, 256>>>(Wk, muc, sic, Wc, D, U, scale);
    build_mask_kernel<<<U, 256>>>(Wr, mup, sip, Wp, U, U, scale);

    // 2) Z = X @ Wc + bias -> straight into d_out.
    {
        dim3 grid(U / 128, (B * T) / 128);
        gemm_big_kernel<<<grid, 256>>>(X, D, Wc, bias, out, U, U, D);
    }

    // 3) Persistent recurrent scan (single kernel, all T steps).
    {
        dim3 grid(U / 32, B / 64);   // 32 x 4 = 128 CTAs
        scan_kernel<<<grid, 256, scan_smem>>>(out, h0, Wp, T, U);
    }
}